// round 8
// baseline (speedup 1.0000x reference)
#include <cuda_runtime.h>
#include <cstdint>

#define NN 50000
#define EE 600000
#define FF 128
#define RR 4

// ---------------- scratch (static device globals; no allocation) ----------------
__device__ __align__(16) float g_agg[(size_t)RR * NN * FF];
__device__ __align__(16) float g_h[(size_t)RR * NN * FF];
__device__ float g_sum[RR * FF];
__device__ float g_sumsq[RR * FF];
__device__ float g_scale[RR * FF];
__device__ float g_shift[RR * FF];
__device__ float g_bias2[FF];
// 9 weight matrices (W1 r0..3, Wself, W2 r0..3), each {hi 8192 u32, lo 8192 u32},
// transposed to [n][k] bf16-pair layout with XOR swizzle (matches smem layout).
__device__ __align__(16) unsigned g_wb[9u * 16384u];

// ---------------- helpers ---------------------------------------------------------
__device__ __forceinline__ void split2(float a0, float a1, unsigned& hi, unsigned& lo) {
    asm("cvt.rn.bf16x2.f32 %0, %1, %2;" : "=r"(hi) : "f"(a1), "f"(a0));
    float h0 = __uint_as_float(hi << 16);
    float h1 = __uint_as_float(hi & 0xffff0000u);
    float l0 = a0 - h0, l1 = a1 - h1;
    asm("cvt.rn.bf16x2.f32 %0, %1, %2;" : "=r"(lo) : "f"(l1), "f"(l0));
}

__device__ __forceinline__ uint32_t smem_u32(const void* p) {
    uint32_t a;
    asm("{ .reg .u64 t; cvta.to.shared.u64 t, %1; cvt.u32.u64 %0, t; }" : "=r"(a) : "l"(p));
    return a;
}

#define MMA_BF16(c, a, b)                                                          \
    asm volatile(                                                                  \
        "mma.sync.aligned.m16n8k16.row.col.f32.bf16.bf16.f32 "                     \
        "{%0,%1,%2,%3}, {%4,%5,%6,%7}, {%8,%9}, {%0,%1,%2,%3};"                    \
        : "+f"((c)[0]), "+f"((c)[1]), "+f"((c)[2]), "+f"((c)[3])                   \
        : "r"((a)[0]), "r"((a)[1]), "r"((a)[2]), "r"((a)[3]), "r"((b)[0]),         \
          "r"((b)[1]))

#define LDSM4(r, a)                                                                \
    asm volatile("ldmatrix.sync.aligned.m8n8.x4.shared.b16 {%0,%1,%2,%3}, [%4];"   \
                 : "=r"((r)[0]), "=r"((r)[1]), "=r"((r)[2]), "=r"((r)[3])          \
                 : "r"(a))

#define LDSM2(r, a)                                                                \
    asm volatile("ldmatrix.sync.aligned.m8n8.x2.shared.b16 {%0,%1}, [%2];"         \
                 : "=r"((r)[0]), "=r"((r)[1])                                      \
                 : "r"(a))

// ---------------- init: g_agg[r] = x, zero stats -----------------------------------
__global__ void init_kernel(const float4* __restrict__ x4) {
    const int PER = NN * FF / 4;
    int i = blockIdx.x * blockDim.x + threadIdx.x;
    int rel = blockIdx.y;
    if (i < PER) ((float4*)g_agg)[(size_t)rel * PER + i] = x4[i];
    if (rel == 0 && i < RR * FF) {
        g_sum[i] = 0.f;
        g_sumsq[i] = 0.f;
    }
}

// ---------------- scatter: vector atomics (validated in R1) ------------------------
__global__ void scatter_kernel(const int* __restrict__ ei, const int* __restrict__ et,
                               const float4* __restrict__ x4) {
    int w = (blockIdx.x * blockDim.x + threadIdx.x) >> 5;
    int lane = threadIdx.x & 31;
    if (w >= EE) return;
    int dst = ei[w];
    int src = ei[EE + w];
    int r = et[w];
    float4 v = x4[(size_t)src * 32 + lane];
    float* p = g_agg + (((size_t)r * NN + dst) * FF + lane * 4);
    asm volatile("red.global.add.v4.f32 [%0], {%1,%2,%3,%4};"
                 :: "l"(p), "f"(v.x), "f"(v.y), "f"(v.z), "f"(v.w) : "memory");
}

// ---------------- weight prep: transpose + bf16 split + swizzle --------------------
__global__ void prep_w_kernel(const float* __restrict__ W1, const float* __restrict__ Wself,
                              const float* __restrict__ W2) {
    int m = blockIdx.x;  // 0..8
    const float* W = (m < 4) ? (W1 + m * (FF * FF))
                             : ((m == 4) ? Wself : (W2 + (m - 5) * (FF * FF)));
    unsigned* outh = g_wb + (size_t)m * 16384u;
    unsigned* outl = outh + 8192;
    for (int q = threadIdx.x; q < 8192; q += blockDim.x) {
        int n = q & 127, ku = q >> 7;
        float a0 = W[(2 * ku) * FF + n];
        float a1 = W[(2 * ku + 1) * FF + n];
        unsigned hi, lo;
        split2(a0, a1, hi, lo);
        unsigned idx = n * 64 + (ku ^ ((n & 7) << 2));
        outh[idx] = hi;
        outl[idx] = lo;
    }
}

// ---------------- HMMA gemm machinery ----------------------------------------------
// smem (u32 units): Ah[0,8192) Al[8192,16384) Bh[16384,24576) Bl[24576,32768)
// layout: buf[row*64 + (ku ^ ((row&7)<<2))], row = M-row (A) or N-col (B), ku = k/2.
#define SMEM_BYTES 131072

__device__ __forceinline__ void copy_b(unsigned* Bh, int mat, int tid) {
    const float4* src = (const float4*)(g_wb + (size_t)mat * 16384u);
    float4* dst = (float4*)Bh;
#pragma unroll
    for (int it = 0; it < 16; ++it) dst[it * 256 + tid] = src[it * 256 + tid];
}

// per-lane ldmatrix row bases + swizzle params.
// A: row = wm + (lane&15), ku0 = (lane>>4)<<2;  mi adds 4096B.
// B: n   = wn + (lane&7),  ku0 = ((lane>>3)&1)<<2; nj adds 2048B.
// swizzle XOR (ku bits): sw = (lane&7)<<2  (same for A and B since row&7 == lane&7).
__device__ __forceinline__ void frag_bases(uint32_t smb, int lane, int wm, int wn,
                                           uint32_t& arow, uint32_t& brow,
                                           uint32_t& aku0, uint32_t& bku0, uint32_t& sw) {
    arow = smb + (uint32_t)(wm + (lane & 15)) * 256u;
    brow = smb + 65536u + (uint32_t)(wn + (lane & 7)) * 256u;
    aku0 = ((uint32_t)(lane >> 4)) << 2;
    bku0 = (((uint32_t)(lane >> 3)) & 1u) << 2;
    sw = ((uint32_t)(lane & 7)) << 2;
}

__device__ __forceinline__ void mma_tile(float (*acc)[4][4], uint32_t arow, uint32_t brow,
                                         uint32_t aku0, uint32_t bku0, uint32_t sw) {
#pragma unroll
    for (int kc = 0; kc < 8; ++kc) {
        uint32_t ak = ((aku0 + 8u * kc) ^ sw) << 2;  // byte offset within row
        uint32_t bk = ((bku0 + 8u * kc) ^ sw) << 2;
        unsigned bh[4][2], bl[4][2];
#pragma unroll
        for (int nj = 0; nj < 4; ++nj) {
            LDSM2(bh[nj], brow + nj * 2048u + bk);
            LDSM2(bl[nj], brow + 32768u + nj * 2048u + bk);
        }
#pragma unroll
        for (int mi = 0; mi < 4; ++mi) {
            unsigned ah[4], al[4];
            LDSM4(ah, arow + mi * 4096u + ak);
            LDSM4(al, arow + 32768u + mi * 4096u + ak);
#pragma unroll
            for (int nj = 0; nj < 4; ++nj) {
                MMA_BF16(acc[mi][nj], ah, bh[nj]);
                MMA_BF16(acc[mi][nj], ah, bl[nj]);
                MMA_BF16(acc[mi][nj], al, bh[nj]);
            }
        }
    }
}

// ---------------- GEMM1: g_h[r] = g_agg[r] @ W1[r] + b1[r], fused BN stats ---------
__global__ __launch_bounds__(256, 1) void gemm1_tc(const float* __restrict__ b1g) {
    extern __shared__ unsigned sm[];
    unsigned* Ah = sm;
    unsigned* Al = sm + 8192;
    unsigned* Bh = sm + 16384;
    const int tid = threadIdx.x, wid = tid >> 5, lane = tid & 31;
    const int gq = lane >> 2, tq = lane & 3;
    const int wm = (wid & 1) * 64, wn = (wid >> 1) * 32;
    const int r = blockIdx.y, row0 = blockIdx.x * 128;

    copy_b(Bh, r, tid);

    const float* A = g_agg + (size_t)r * (NN * FF);
#pragma unroll
    for (int it = 0; it < 16; ++it) {
        int q = it * 256 + tid;
        int row = q >> 5, c4 = q & 31;
        float4 v = make_float4(0.f, 0.f, 0.f, 0.f);
        int grow = row0 + row;
        if (grow < NN) v = ((const float4*)A)[(size_t)grow * 32 + c4];
        unsigned h0, l0, h1, l1;
        split2(v.x, v.y, h0, l0);
        split2(v.z, v.w, h1, l1);
        int idx = row * 64 + ((c4 * 2) ^ ((row & 7) << 2));
        Ah[idx] = h0; Ah[idx + 1] = h1;
        Al[idx] = l0; Al[idx + 1] = l1;
    }
    __syncthreads();

    float acc[4][4][4];
#pragma unroll
    for (int mi = 0; mi < 4; ++mi)
#pragma unroll
        for (int nj = 0; nj < 4; ++nj)
#pragma unroll
            for (int c = 0; c < 4; ++c) acc[mi][nj][c] = 0.f;

    uint32_t arow, brow, aku0, bku0, sw;
    frag_bases(smem_u32(sm), lane, wm, wn, arow, brow, aku0, bku0, sw);
    mma_tile(acc, arow, brow, aku0, bku0, sw);

    // add bias into accumulators (so stats see h directly)
    const float* bias = b1g + r * FF;
#pragma unroll
    for (int nj = 0; nj < 4; ++nj) {
        int col = wn + nj * 8 + 2 * tq;
        float bx = bias[col], by = bias[col + 1];
#pragma unroll
        for (int mi = 0; mi < 4; ++mi) {
            acc[mi][nj][0] += bx; acc[mi][nj][1] += by;
            acc[mi][nj][2] += bx; acc[mi][nj][3] += by;
        }
    }

    // store h
    float* H = g_h + (size_t)r * (NN * FF);
#pragma unroll
    for (int mi = 0; mi < 4; ++mi) {
        int ra = row0 + wm + mi * 16 + gq;
#pragma unroll
        for (int nj = 0; nj < 4; ++nj) {
            int col = wn + nj * 8 + 2 * tq;
            if (ra < NN)
                *(float2*)(H + (size_t)ra * FF + col) = make_float2(acc[mi][nj][0], acc[mi][nj][1]);
            if (ra + 8 < NN)
                *(float2*)(H + (size_t)(ra + 8) * FF + col) = make_float2(acc[mi][nj][2], acc[mi][nj][3]);
        }
    }

    // fused BN stats: per-column sum / sumsq of this tile
    __syncthreads();
    float* red = (float*)sm;  // [0,128) sum, [128,256) sumsq
    red[tid] = 0.f;
    __syncthreads();
#pragma unroll
    for (int nj = 0; nj < 4; ++nj)
#pragma unroll
        for (int par = 0; par < 2; ++par) {
            int col = wn + nj * 8 + 2 * tq + par;
            float s = 0.f, q = 0.f;
#pragma unroll
            for (int mi = 0; mi < 4; ++mi) {
                int ra = row0 + wm + mi * 16 + gq;
                if (ra < NN) {
                    float v = acc[mi][nj][par];
                    s += v; q = fmaf(v, v, q);
                }
                if (ra + 8 < NN) {
                    float v = acc[mi][nj][2 + par];
                    s += v; q = fmaf(v, v, q);
                }
            }
            atomicAdd(&red[col], s);
            atomicAdd(&red[128 + col], q);
        }
    __syncthreads();
    if (tid < 128) {
        atomicAdd(&g_sum[r * FF + tid], red[tid]);
        atomicAdd(&g_sumsq[r * FF + tid], red[128 + tid]);
    }
}

// ---------------- finalize BN + combined bias ---------------------------------------
__global__ void finalize_kernel(const float* __restrict__ gamma, const float* __restrict__ beta,
                                const float* __restrict__ bself, const float* __restrict__ b2g) {
    int i = threadIdx.x + blockIdx.x * blockDim.x;
    if (i < RR * FF) {
        float inv_n = 1.0f / (float)NN;
        float mean = g_sum[i] * inv_n;
        float var = g_sumsq[i] * inv_n - mean * mean;
        if (var < 0.f) var = 0.f;
        float sc = gamma[i] * rsqrtf(var + 1e-5f);
        g_scale[i] = sc;
        g_shift[i] = beta[i] - mean * sc;
    }
    if (i < FF) {
        float b = bself[i];
#pragma unroll
        for (int rr = 0; rr < RR; ++rr) b += b2g[rr * FF + i];
        g_bias2[i] = b;
    }
}

// ---------------- GEMM2: out = x@Wself + sum_r relu(bn(h_r))@W2[r] + bias ----------
__global__ __launch_bounds__(256, 1) void gemm2_tc(const float* __restrict__ x,
                                                   float* __restrict__ out) {
    extern __shared__ unsigned sm[];
    unsigned* Ah = sm;
    unsigned* Al = sm + 8192;
    unsigned* Bh = sm + 16384;
    const int tid = threadIdx.x, wid = tid >> 5, lane = tid & 31;
    const int gq = lane >> 2, tq = lane & 3;
    const int wm = (wid & 1) * 64, wn = (wid >> 1) * 32;
    const int row0 = blockIdx.x * 128;

    float acc[4][4][4];
#pragma unroll
    for (int mi = 0; mi < 4; ++mi)
#pragma unroll
        for (int nj = 0; nj < 4; ++nj)
#pragma unroll
            for (int c = 0; c < 4; ++c) acc[mi][nj][c] = 0.f;

    uint32_t arow, brow, aku0, bku0, sw;
    frag_bases(smem_u32(sm), lane, wm, wn, arow, brow, aku0, bku0, sw);

    for (int rel = 0; rel < 5; ++rel) {
        __syncthreads();
        copy_b(Bh, 4 + rel, tid);

        const float* A = (rel == 0) ? x : (g_h + (size_t)(rel - 1) * (NN * FF));
        const float* sc = g_scale + (rel - 1) * FF;
        const float* sf = g_shift + (rel - 1) * FF;
#pragma unroll
        for (int it = 0; it < 16; ++it) {
            int q = it * 256 + tid;
            int row = q >> 5, c4 = q & 31, k4 = c4 * 4;
            float4 v = make_float4(0.f, 0.f, 0.f, 0.f);
            int grow = row0 + row;
            if (grow < NN) {
                v = ((const float4*)A)[(size_t)grow * 32 + c4];
                if (rel > 0) {
                    v.x = fmaxf(fmaf(v.x, sc[k4 + 0], sf[k4 + 0]), 0.f);
                    v.y = fmaxf(fmaf(v.y, sc[k4 + 1], sf[k4 + 1]), 0.f);
                    v.z = fmaxf(fmaf(v.z, sc[k4 + 2], sf[k4 + 2]), 0.f);
                    v.w = fmaxf(fmaf(v.w, sc[k4 + 3], sf[k4 + 3]), 0.f);
                }
            }
            unsigned h0, l0, h1, l1;
            split2(v.x, v.y, h0, l0);
            split2(v.z, v.w, h1, l1);
            int idx = row * 64 + ((c4 * 2) ^ ((row & 7) << 2));
            Ah[idx] = h0; Ah[idx + 1] = h1;
            Al[idx] = l0; Al[idx + 1] = l1;
        }
        __syncthreads();

        mma_tile(acc, arow, brow, aku0, bku0, sw);
    }

#pragma unroll
    for (int mi = 0; mi < 4; ++mi) {
        int ra = row0 + wm + mi * 16 + gq;
#pragma unroll
        for (int nj = 0; nj < 4; ++nj) {
            int col = wn + nj * 8 + 2 * tq;
            float bx = g_bias2[col], by = g_bias2[col + 1];
            if (ra < NN)
                *(float2*)(out + (size_t)ra * FF + col) =
                    make_float2(acc[mi][nj][0] + bx, acc[mi][nj][1] + by);
            if (ra + 8 < NN)
                *(float2*)(out + (size_t)(ra + 8) * FF + col) =
                    make_float2(acc[mi][nj][2] + bx, acc[mi][nj][3] + by);
        }
    }
}

// ---------------- launch ---------------------------------------------------------
extern "C" void kernel_launch(void* const* d_in, const int* in_sizes, int n_in,
                              void* d_out, int out_size) {
    const float* x     = (const float*)d_in[0];
    const int*   ei    = (const int*)d_in[1];
    const int*   et    = (const int*)d_in[2];
    const float* Wself = (const float*)d_in[3];
    const float* bself = (const float*)d_in[4];
    const float* W1    = (const float*)d_in[5];
    const float* b1    = (const float*)d_in[6];
    const float* gamma = (const float*)d_in[7];
    const float* beta  = (const float*)d_in[8];
    const float* W2    = (const float*)d_in[9];
    const float* b2    = (const float*)d_in[10];
    float* out = (float*)d_out;

    cudaFuncSetAttribute(gemm1_tc, cudaFuncAttributeMaxDynamicSharedMemorySize, SMEM_BYTES);
    cudaFuncSetAttribute(gemm2_tc, cudaFuncAttributeMaxDynamicSharedMemorySize, SMEM_BYTES);

    const int G1 = (NN + 127) / 128;  // 391
    const int PER4 = NN * FF / 4;

    prep_w_kernel<<<9, 256>>>(W1, Wself, W2);
    init_kernel<<<dim3((PER4 + 255) / 256, RR), 256>>>((const float4*)x);
    scatter_kernel<<<(EE * 32) / 256, 256>>>(ei, et, (const float4*)x);
    gemm1_tc<<<dim3(G1, RR), 256, SMEM_BYTES>>>(b1);       // <- 4th launch: profiled
    finalize_kernel<<<2, 256>>>(gamma, beta, bself, b2);
    gemm2_tc<<<G1, 256, SMEM_BYTES>>>(x, out);
}

// round 9
// speedup vs baseline: 1.2280x; 1.2280x over previous
#include <cuda_runtime.h>
#include <cstdint>

#define NN 50000
#define EE 600000
#define FF 128
#define RR 4

// ---------------- scratch (static device globals; no allocation) ----------------
__device__ __align__(16) float g_agg[(size_t)RR * NN * FF];
__device__ __align__(16) float g_h[(size_t)RR * NN * FF];
__device__ float g_sum[RR * FF];
__device__ float g_sumsq[RR * FF];
__device__ float g_scale[RR * FF];
__device__ float g_shift[RR * FF];
__device__ float g_bias2[FF];
// 9 weight matrices (W1 r0..3, Wself, W2 r0..3), each {hi 8192 u32, lo 8192 u32},
// transposed to [n][k] bf16-pair layout with XOR swizzle (matches smem layout).
__device__ __align__(16) unsigned g_wb[9u * 16384u];

// ---------------- helpers ---------------------------------------------------------
__device__ __forceinline__ void split2(float a0, float a1, unsigned& hi, unsigned& lo) {
    asm("cvt.rn.bf16x2.f32 %0, %1, %2;" : "=r"(hi) : "f"(a1), "f"(a0));
    float h0 = __uint_as_float(hi << 16);
    float h1 = __uint_as_float(hi & 0xffff0000u);
    float l0 = a0 - h0, l1 = a1 - h1;
    asm("cvt.rn.bf16x2.f32 %0, %1, %2;" : "=r"(lo) : "f"(l1), "f"(l0));
}

__device__ __forceinline__ uint32_t smem_u32(const void* p) {
    uint32_t a;
    asm("{ .reg .u64 t; cvta.to.shared.u64 t, %1; cvt.u32.u64 %0, t; }" : "=r"(a) : "l"(p));
    return a;
}

#define MMA_BF16(c, a, b)                                                          \
    asm volatile(                                                                  \
        "mma.sync.aligned.m16n8k16.row.col.f32.bf16.bf16.f32 "                     \
        "{%0,%1,%2,%3}, {%4,%5,%6,%7}, {%8,%9}, {%0,%1,%2,%3};"                    \
        : "+f"((c)[0]), "+f"((c)[1]), "+f"((c)[2]), "+f"((c)[3])                   \
        : "r"((a)[0]), "r"((a)[1]), "r"((a)[2]), "r"((a)[3]), "r"((b)[0]),         \
          "r"((b)[1]))

#define LDSM4(r, a)                                                                \
    asm volatile("ldmatrix.sync.aligned.m8n8.x4.shared.b16 {%0,%1,%2,%3}, [%4];"   \
                 : "=r"((r)[0]), "=r"((r)[1]), "=r"((r)[2]), "=r"((r)[3])          \
                 : "r"(a))

#define LDSM2(r, a)                                                                \
    asm volatile("ldmatrix.sync.aligned.m8n8.x2.shared.b16 {%0,%1}, [%2];"         \
                 : "=r"((r)[0]), "=r"((r)[1])                                      \
                 : "r"(a))

#define CP16(dst, src)                                                             \
    asm volatile("cp.async.cg.shared.global [%0], [%1], 16;" :: "r"(dst), "l"(src))
#define CP_WAIT()                                                                  \
    asm volatile("cp.async.commit_group;\n\tcp.async.wait_group 0;" ::: "memory")

// ---------------- scatter: vector atomics ------------------------------------------
__global__ void scatter_kernel(const int* __restrict__ ei, const int* __restrict__ et,
                               const float4* __restrict__ x4) {
    int w = (blockIdx.x * blockDim.x + threadIdx.x) >> 5;
    int lane = threadIdx.x & 31;
    if (w >= EE) return;
    int dst = ei[w];
    int src = ei[EE + w];
    int r = et[w];
    float4 v = x4[(size_t)src * 32 + lane];
    float* p = g_agg + (((size_t)r * NN + dst) * FF + lane * 4);
    asm volatile("red.global.add.v4.f32 [%0], {%1,%2,%3,%4};"
                 :: "l"(p), "f"(v.x), "f"(v.y), "f"(v.z), "f"(v.w) : "memory");
}

// ---------------- weight prep: transpose + bf16 split + swizzle (+ zero stats) -----
__global__ void prep_w_kernel(const float* __restrict__ W1, const float* __restrict__ Wself,
                              const float* __restrict__ W2) {
    int m = blockIdx.x;  // 0..8
    if (m == 0) {
        for (int i = threadIdx.x; i < RR * FF; i += blockDim.x) {
            g_sum[i] = 0.f;
            g_sumsq[i] = 0.f;
        }
    }
    const float* W = (m < 4) ? (W1 + m * (FF * FF))
                             : ((m == 4) ? Wself : (W2 + (m - 5) * (FF * FF)));
    unsigned* outh = g_wb + (size_t)m * 16384u;
    unsigned* outl = outh + 8192;
    for (int q = threadIdx.x; q < 8192; q += blockDim.x) {
        int n = q & 127, ku = q >> 7;
        float a0 = W[(2 * ku) * FF + n];
        float a1 = W[(2 * ku + 1) * FF + n];
        unsigned hi, lo;
        split2(a0, a1, hi, lo);
        unsigned idx = n * 64 + (ku ^ ((n & 7) << 2));
        outh[idx] = hi;
        outl[idx] = lo;
    }
}

// ---------------- HMMA gemm machinery ----------------------------------------------
// M-tile 64 x N 128. smem u32 units: Ah[0,4096) Al[4096,8192) Bh[8192,16384) Bl[16384,24576)
// layout: buf[row*64 + (ku ^ ((row&7)<<2))], row = M-row (A) or N-col (B), ku = k/2.
#define SMEM_BYTES 98304

__device__ __forceinline__ void copy_b_async(uint32_t smb, int mat, int tid) {
    const float4* src = (const float4*)(g_wb + (size_t)mat * 16384u);
    uint32_t dst = smb + 32768u + (uint32_t)tid * 16u;
#pragma unroll
    for (int it = 0; it < 16; ++it) CP16(dst + it * 4096u, src + it * 256 + tid);
}

// per-lane ldmatrix row bases + swizzle params.
__device__ __forceinline__ void frag_bases(uint32_t smb, int lane, int wm, int wn,
                                           uint32_t& arow, uint32_t& brow,
                                           uint32_t& aku0, uint32_t& bku0, uint32_t& sw) {
    arow = smb + (uint32_t)(wm + (lane & 15)) * 256u;
    brow = smb + 32768u + (uint32_t)(wn + (lane & 7)) * 256u;
    aku0 = ((uint32_t)(lane >> 4)) << 2;
    bku0 = (((uint32_t)(lane >> 3)) & 1u) << 2;
    sw = ((uint32_t)(lane & 7)) << 2;
}

__device__ __forceinline__ void mma_tile(float (*acc)[4][4], uint32_t arow, uint32_t brow,
                                         uint32_t aku0, uint32_t bku0, uint32_t sw) {
#pragma unroll
    for (int kc = 0; kc < 8; ++kc) {
        uint32_t ak = ((aku0 + 8u * kc) ^ sw) << 2;
        uint32_t bk = ((bku0 + 8u * kc) ^ sw) << 2;
        unsigned bh[4][2], bl[4][2];
#pragma unroll
        for (int nj = 0; nj < 4; ++nj) {
            LDSM2(bh[nj], brow + nj * 2048u + bk);
            LDSM2(bl[nj], brow + 32768u + nj * 2048u + bk);
        }
#pragma unroll
        for (int mi = 0; mi < 2; ++mi) {
            unsigned ah[4], al[4];
            LDSM4(ah, arow + mi * 4096u + ak);
            LDSM4(al, arow + 16384u + mi * 4096u + ak);
#pragma unroll
            for (int nj = 0; nj < 4; ++nj) {
                MMA_BF16(acc[mi][nj], ah, bh[nj]);
                MMA_BF16(acc[mi][nj], ah, bl[nj]);
                MMA_BF16(acc[mi][nj], al, bh[nj]);
            }
        }
    }
}

// ---------------- GEMM1: g_h[r] = (x + agg[r]) @ W1[r] + b1[r], fused BN stats -----
__global__ __launch_bounds__(256, 2) void gemm1_tc(const float4* __restrict__ x4,
                                                   const float* __restrict__ b1g) {
    extern __shared__ unsigned sm[];
    unsigned* Ah = sm;
    unsigned* Al = sm + 4096;
    const uint32_t smb = smem_u32(sm);
    const int tid = threadIdx.x, wid = tid >> 5, lane = tid & 31;
    const int gq = lane >> 2, tq = lane & 3;
    const int wm = (wid & 1) * 32, wn = (wid >> 1) * 32;
    const int r = blockIdx.y, row0 = blockIdx.x * 64;

    copy_b_async(smb, r, tid);

    const float4* A4 = (const float4*)(g_agg + (size_t)r * (NN * FF));
#pragma unroll
    for (int it = 0; it < 8; ++it) {
        int q = it * 256 + tid;
        int row = q >> 5, c4 = q & 31;
        float4 v = make_float4(0.f, 0.f, 0.f, 0.f);
        int grow = row0 + row;
        if (grow < NN) {
            v = A4[(size_t)grow * 32 + c4];
            float4 xv = x4[(size_t)grow * 32 + c4];
            v.x += xv.x; v.y += xv.y; v.z += xv.z; v.w += xv.w;
        }
        unsigned h0, l0, h1, l1;
        split2(v.x, v.y, h0, l0);
        split2(v.z, v.w, h1, l1);
        int idx = row * 64 + ((c4 * 2) ^ ((row & 7) << 2));
        Ah[idx] = h0; Ah[idx + 1] = h1;
        Al[idx] = l0; Al[idx + 1] = l1;
    }
    CP_WAIT();
    __syncthreads();

    float acc[2][4][4];
#pragma unroll
    for (int mi = 0; mi < 2; ++mi)
#pragma unroll
        for (int nj = 0; nj < 4; ++nj)
#pragma unroll
            for (int c = 0; c < 4; ++c) acc[mi][nj][c] = 0.f;

    uint32_t arow, brow, aku0, bku0, sw;
    frag_bases(smb, lane, wm, wn, arow, brow, aku0, bku0, sw);
    mma_tile(acc, arow, brow, aku0, bku0, sw);

    // add bias into accumulators (so stats see h directly)
    const float* bias = b1g + r * FF;
#pragma unroll
    for (int nj = 0; nj < 4; ++nj) {
        int col = wn + nj * 8 + 2 * tq;
        float bx = bias[col], by = bias[col + 1];
#pragma unroll
        for (int mi = 0; mi < 2; ++mi) {
            acc[mi][nj][0] += bx; acc[mi][nj][1] += by;
            acc[mi][nj][2] += bx; acc[mi][nj][3] += by;
        }
    }

    // store h
    float* H = g_h + (size_t)r * (NN * FF);
#pragma unroll
    for (int mi = 0; mi < 2; ++mi) {
        int ra = row0 + wm + mi * 16 + gq;
#pragma unroll
        for (int nj = 0; nj < 4; ++nj) {
            int col = wn + nj * 8 + 2 * tq;
            if (ra < NN)
                *(float2*)(H + (size_t)ra * FF + col) = make_float2(acc[mi][nj][0], acc[mi][nj][1]);
            if (ra + 8 < NN)
                *(float2*)(H + (size_t)(ra + 8) * FF + col) = make_float2(acc[mi][nj][2], acc[mi][nj][3]);
        }
    }

    // fused BN stats: per-column sum / sumsq of this tile
    __syncthreads();
    float* red = (float*)sm;  // [0,128) sum, [128,256) sumsq
    red[tid] = 0.f;
    __syncthreads();
#pragma unroll
    for (int nj = 0; nj < 4; ++nj)
#pragma unroll
        for (int par = 0; par < 2; ++par) {
            int col = wn + nj * 8 + 2 * tq + par;
            float s = 0.f, q = 0.f;
#pragma unroll
            for (int mi = 0; mi < 2; ++mi) {
                int ra = row0 + wm + mi * 16 + gq;
                if (ra < NN) {
                    float v = acc[mi][nj][par];
                    s += v; q = fmaf(v, v, q);
                }
                if (ra + 8 < NN) {
                    float v = acc[mi][nj][2 + par];
                    s += v; q = fmaf(v, v, q);
                }
            }
            atomicAdd(&red[col], s);
            atomicAdd(&red[128 + col], q);
        }
    __syncthreads();
    if (tid < 128) {
        atomicAdd(&g_sum[r * FF + tid], red[tid]);
        atomicAdd(&g_sumsq[r * FF + tid], red[128 + tid]);
    }
}

// ---------------- finalize BN + combined bias ---------------------------------------
__global__ void finalize_kernel(const float* __restrict__ gamma, const float* __restrict__ beta,
                                const float* __restrict__ bself, const float* __restrict__ b2g) {
    int i = threadIdx.x + blockIdx.x * blockDim.x;
    if (i < RR * FF) {
        float inv_n = 1.0f / (float)NN;
        float mean = g_sum[i] * inv_n;
        float var = g_sumsq[i] * inv_n - mean * mean;
        if (var < 0.f) var = 0.f;
        float sc = gamma[i] * rsqrtf(var + 1e-5f);
        g_scale[i] = sc;
        g_shift[i] = beta[i] - mean * sc;
    }
    if (i < FF) {
        float b = bself[i];
#pragma unroll
        for (int rr = 0; rr < RR; ++rr) b += b2g[rr * FF + i];
        g_bias2[i] = b;
    }
}

// ---------------- GEMM2: out = x@Wself + sum_r relu(bn(h_r))@W2[r] + bias ----------
__global__ __launch_bounds__(256, 2) void gemm2_tc(const float* __restrict__ x,
                                                   float* __restrict__ out) {
    extern __shared__ unsigned sm[];
    unsigned* Ah = sm;
    unsigned* Al = sm + 4096;
    const uint32_t smb = smem_u32(sm);
    const int tid = threadIdx.x, wid = tid >> 5, lane = tid & 31;
    const int gq = lane >> 2, tq = lane & 3;
    const int wm = (wid & 1) * 32, wn = (wid >> 1) * 32;
    const int row0 = blockIdx.x * 64;

    float acc[2][4][4];
#pragma unroll
    for (int mi = 0; mi < 2; ++mi)
#pragma unroll
        for (int nj = 0; nj < 4; ++nj)
#pragma unroll
            for (int c = 0; c < 4; ++c) acc[mi][nj][c] = 0.f;

    uint32_t arow, brow, aku0, bku0, sw;
    frag_bases(smb, lane, wm, wn, arow, brow, aku0, bku0, sw);

    for (int rel = 0; rel < 5; ++rel) {
        __syncthreads();
        copy_b_async(smb, 4 + rel, tid);

        const float* A = (rel == 0) ? x : (g_h + (size_t)(rel - 1) * (NN * FF));
        const float* sc = g_scale + (rel - 1) * FF;
        const float* sf = g_shift + (rel - 1) * FF;
#pragma unroll
        for (int it = 0; it < 8; ++it) {
            int q = it * 256 + tid;
            int row = q >> 5, c4 = q & 31, k4 = c4 * 4;
            float4 v = make_float4(0.f, 0.f, 0.f, 0.f);
            int grow = row0 + row;
            if (grow < NN) {
                v = ((const float4*)A)[(size_t)grow * 32 + c4];
                if (rel > 0) {
                    v.x = fmaxf(fmaf(v.x, sc[k4 + 0], sf[k4 + 0]), 0.f);
                    v.y = fmaxf(fmaf(v.y, sc[k4 + 1], sf[k4 + 1]), 0.f);
                    v.z = fmaxf(fmaf(v.z, sc[k4 + 2], sf[k4 + 2]), 0.f);
                    v.w = fmaxf(fmaf(v.w, sc[k4 + 3], sf[k4 + 3]), 0.f);
                }
            }
            unsigned h0, l0, h1, l1;
            split2(v.x, v.y, h0, l0);
            split2(v.z, v.w, h1, l1);
            int idx = row * 64 + ((c4 * 2) ^ ((row & 7) << 2));
            Ah[idx] = h0; Ah[idx + 1] = h1;
            Al[idx] = l0; Al[idx + 1] = l1;
        }
        CP_WAIT();
        __syncthreads();

        mma_tile(acc, arow, brow, aku0, bku0, sw);
    }

#pragma unroll
    for (int mi = 0; mi < 2; ++mi) {
        int ra = row0 + wm + mi * 16 + gq;
#pragma unroll
        for (int nj = 0; nj < 4; ++nj) {
            int col = wn + nj * 8 + 2 * tq;
            float bx = g_bias2[col], by = g_bias2[col + 1];
            if (ra < NN)
                *(float2*)(out + (size_t)ra * FF + col) =
                    make_float2(acc[mi][nj][0] + bx, acc[mi][nj][1] + by);
            if (ra + 8 < NN)
                *(float2*)(out + (size_t)(ra + 8) * FF + col) =
                    make_float2(acc[mi][nj][2] + bx, acc[mi][nj][3] + by);
        }
    }
}

// ---------------- launch ---------------------------------------------------------
extern "C" void kernel_launch(void* const* d_in, const int* in_sizes, int n_in,
                              void* d_out, int out_size) {
    const float* x     = (const float*)d_in[0];
    const int*   ei    = (const int*)d_in[1];
    const int*   et    = (const int*)d_in[2];
    const float* Wself = (const float*)d_in[3];
    const float* bself = (const float*)d_in[4];
    const float* W1    = (const float*)d_in[5];
    const float* b1    = (const float*)d_in[6];
    const float* gamma = (const float*)d_in[7];
    const float* beta  = (const float*)d_in[8];
    const float* W2    = (const float*)d_in[9];
    const float* b2    = (const float*)d_in[10];
    float* out = (float*)d_out;

    void* p_agg = nullptr;
    cudaGetSymbolAddress(&p_agg, g_agg);
    cudaMemsetAsync(p_agg, 0, (size_t)RR * NN * FF * sizeof(float));

    cudaFuncSetAttribute(gemm1_tc, cudaFuncAttributeMaxDynamicSharedMemorySize, SMEM_BYTES);
    cudaFuncSetAttribute(gemm2_tc, cudaFuncAttributeMaxDynamicSharedMemorySize, SMEM_BYTES);

    const int G1 = (NN + 63) / 64;  // 782

    prep_w_kernel<<<9, 256>>>(W1, Wself, W2);
    scatter_kernel<<<(EE * 32) / 256, 256>>>(ei, et, (const float4*)x);
    gemm1_tc<<<dim3(G1, RR), 256, SMEM_BYTES>>>((const float4*)x, b1);
    finalize_kernel<<<2, 256>>>(gamma, beta, bself, b2);
    gemm2_tc<<<G1, 256, SMEM_BYTES>>>(x, out);
}

// round 10
// speedup vs baseline: 1.2987x; 1.0576x over previous
#include <cuda_runtime.h>
#include <cstdint>

#define NN 50000
#define EE 600000
#define FF 128
#define RR 4

// ---------------- scratch (static device globals; no allocation) ----------------
__device__ __align__(16) float g_agg[(size_t)RR * NN * FF];
__device__ __align__(16) float g_h[(size_t)RR * NN * FF];
__device__ float g_sum[RR * FF];
__device__ float g_sumsq[RR * FF];
// 9 weight matrices (W1 r0..3, Wself, W2 r0..3), each {hi 8192 u32, lo 8192 u32},
// transposed to [n][k] bf16-pair layout with XOR swizzle (matches smem layout).
__device__ __align__(16) unsigned g_wb[9u * 16384u];

// ---------------- helpers ---------------------------------------------------------
__device__ __forceinline__ void split2(float a0, float a1, unsigned& hi, unsigned& lo) {
    asm("cvt.rn.bf16x2.f32 %0, %1, %2;" : "=r"(hi) : "f"(a1), "f"(a0));
    float h0 = __uint_as_float(hi << 16);
    float h1 = __uint_as_float(hi & 0xffff0000u);
    float l0 = a0 - h0, l1 = a1 - h1;
    asm("cvt.rn.bf16x2.f32 %0, %1, %2;" : "=r"(lo) : "f"(l1), "f"(l0));
}

__device__ __forceinline__ uint32_t smem_u32(const void* p) {
    uint32_t a;
    asm("{ .reg .u64 t; cvta.to.shared.u64 t, %1; cvt.u32.u64 %0, t; }" : "=r"(a) : "l"(p));
    return a;
}

// NOTE: no `volatile` on LDSM/MMA — all effects are expressed via register
// constraints; this lets ptxas software-pipeline fragment loads across MMAs.
#define MMA_BF16(c, a, b)                                                          \
    asm("mma.sync.aligned.m16n8k16.row.col.f32.bf16.bf16.f32 "                     \
        "{%0,%1,%2,%3}, {%4,%5,%6,%7}, {%8,%9}, {%0,%1,%2,%3};"                    \
        : "+f"((c)[0]), "+f"((c)[1]), "+f"((c)[2]), "+f"((c)[3])                   \
        : "r"((a)[0]), "r"((a)[1]), "r"((a)[2]), "r"((a)[3]), "r"((b)[0]),         \
          "r"((b)[1]))

#define LDSM4(r, a)                                                                \
    asm("ldmatrix.sync.aligned.m8n8.x4.shared.b16 {%0,%1,%2,%3}, [%4];"            \
        : "=r"((r)[0]), "=r"((r)[1]), "=r"((r)[2]), "=r"((r)[3])                   \
        : "r"(a))

#define LDSM2(r, a)                                                                \
    asm("ldmatrix.sync.aligned.m8n8.x2.shared.b16 {%0,%1}, [%2];"                  \
        : "=r"((r)[0]), "=r"((r)[1])                                               \
        : "r"(a))

#define CP16(dst, src)                                                             \
    asm volatile("cp.async.cg.shared.global [%0], [%1], 16;" :: "r"(dst), "l"(src))
#define CP_WAIT()                                                                  \
    asm volatile("cp.async.commit_group;\n\tcp.async.wait_group 0;" ::: "memory")

// ---------------- scatter: vector atomics ------------------------------------------
__global__ void scatter_kernel(const int* __restrict__ ei, const int* __restrict__ et,
                               const float4* __restrict__ x4) {
    int w = (blockIdx.x * blockDim.x + threadIdx.x) >> 5;
    int lane = threadIdx.x & 31;
    if (w >= EE) return;
    int dst = ei[w];
    int src = ei[EE + w];
    int r = et[w];
    float4 v = x4[(size_t)src * 32 + lane];
    float* p = g_agg + (((size_t)r * NN + dst) * FF + lane * 4);
    asm volatile("red.global.add.v4.f32 [%0], {%1,%2,%3,%4};"
                 :: "l"(p), "f"(v.x), "f"(v.y), "f"(v.z), "f"(v.w) : "memory");
}

// ---------------- weight prep: transpose + bf16 split + swizzle (+ zero stats) -----
__global__ void prep_w_kernel(const float* __restrict__ W1, const float* __restrict__ Wself,
                              const float* __restrict__ W2) {
    int m = blockIdx.x;  // 0..8
    if (m == 0) {
        for (int i = threadIdx.x; i < RR * FF; i += blockDim.x) {
            g_sum[i] = 0.f;
            g_sumsq[i] = 0.f;
        }
    }
    const float* W = (m < 4) ? (W1 + m * (FF * FF))
                             : ((m == 4) ? Wself : (W2 + (m - 5) * (FF * FF)));
    unsigned* outh = g_wb + (size_t)m * 16384u;
    unsigned* outl = outh + 8192;
    for (int q = threadIdx.x; q < 8192; q += blockDim.x) {
        int n = q & 127, ku = q >> 7;
        float a0 = W[(2 * ku) * FF + n];
        float a1 = W[(2 * ku + 1) * FF + n];
        unsigned hi, lo;
        split2(a0, a1, hi, lo);
        unsigned idx = n * 64 + (ku ^ ((n & 7) << 2));
        outh[idx] = hi;
        outl[idx] = lo;
    }
}

// ---------------- HMMA gemm machinery ----------------------------------------------
// M-tile 64 x N 128. smem u32 units: Ah[0,4096) Al[4096,8192) Bh[8192,16384) Bl[16384,24576)
// gemm2 extras: s_scale[512] @24576, s_shift[512] @25088, s_bias[128] @25600.
#define SMEM1_BYTES 98304
#define SMEM2_BYTES 102912

__device__ __forceinline__ void copy_b_async(uint32_t smb, int mat, int tid) {
    const float4* src = (const float4*)(g_wb + (size_t)mat * 16384u);
    uint32_t dst = smb + 32768u + (uint32_t)tid * 16u;
#pragma unroll
    for (int it = 0; it < 16; ++it) CP16(dst + it * 4096u, src + it * 256 + tid);
}

__device__ __forceinline__ void frag_bases(uint32_t smb, int lane, int wm, int wn,
                                           uint32_t& arow, uint32_t& brow,
                                           uint32_t& aku0, uint32_t& bku0, uint32_t& sw) {
    arow = smb + (uint32_t)(wm + (lane & 15)) * 256u;
    brow = smb + 32768u + (uint32_t)(wn + (lane & 7)) * 256u;
    aku0 = ((uint32_t)(lane >> 4)) << 2;
    bku0 = (((uint32_t)(lane >> 3)) & 1u) << 2;
    sw = ((uint32_t)(lane & 7)) << 2;
}

__device__ __forceinline__ void mma_tile(float (*acc)[4][4], uint32_t arow, uint32_t brow,
                                         uint32_t aku0, uint32_t bku0, uint32_t sw) {
#pragma unroll
    for (int kc = 0; kc < 8; ++kc) {
        uint32_t ak = ((aku0 + 8u * kc) ^ sw) << 2;
        uint32_t bk = ((bku0 + 8u * kc) ^ sw) << 2;
        unsigned bh[4][2], bl[4][2];
#pragma unroll
        for (int nj = 0; nj < 4; ++nj) {
            LDSM2(bh[nj], brow + nj * 2048u + bk);
            LDSM2(bl[nj], brow + 32768u + nj * 2048u + bk);
        }
#pragma unroll
        for (int mi = 0; mi < 2; ++mi) {
            unsigned ah[4], al[4];
            LDSM4(ah, arow + mi * 4096u + ak);
            LDSM4(al, arow + 16384u + mi * 4096u + ak);
#pragma unroll
            for (int nj = 0; nj < 4; ++nj) {
                MMA_BF16(acc[mi][nj], ah, bh[nj]);
                MMA_BF16(acc[mi][nj], ah, bl[nj]);
                MMA_BF16(acc[mi][nj], al, bh[nj]);
            }
        }
    }
}

// ---------------- GEMM1: g_h[r] = (x + agg[r]) @ W1[r] + b1[r], fused BN stats -----
__global__ __launch_bounds__(256, 2) void gemm1_tc(const float4* __restrict__ x4,
                                                   const float* __restrict__ b1g) {
    extern __shared__ unsigned sm[];
    unsigned* Ah = sm;
    unsigned* Al = sm + 4096;
    const uint32_t smb = smem_u32(sm);
    const int tid = threadIdx.x, wid = tid >> 5, lane = tid & 31;
    const int gq = lane >> 2, tq = lane & 3;
    const int wm = (wid & 1) * 32, wn = (wid >> 1) * 32;
    const int r = blockIdx.y, row0 = blockIdx.x * 64;

    copy_b_async(smb, r, tid);

    const float4* A4 = (const float4*)(g_agg + (size_t)r * (NN * FF));
#pragma unroll
    for (int it = 0; it < 8; ++it) {
        int q = it * 256 + tid;
        int row = q >> 5, c4 = q & 31;
        float4 v = make_float4(0.f, 0.f, 0.f, 0.f);
        int grow = row0 + row;
        if (grow < NN) {
            v = A4[(size_t)grow * 32 + c4];
            float4 xv = x4[(size_t)grow * 32 + c4];
            v.x += xv.x; v.y += xv.y; v.z += xv.z; v.w += xv.w;
        }
        unsigned h0, l0, h1, l1;
        split2(v.x, v.y, h0, l0);
        split2(v.z, v.w, h1, l1);
        int idx = row * 64 + ((c4 * 2) ^ ((row & 7) << 2));
        Ah[idx] = h0; Ah[idx + 1] = h1;
        Al[idx] = l0; Al[idx + 1] = l1;
    }
    CP_WAIT();
    __syncthreads();

    float acc[2][4][4];
#pragma unroll
    for (int mi = 0; mi < 2; ++mi)
#pragma unroll
        for (int nj = 0; nj < 4; ++nj)
#pragma unroll
            for (int c = 0; c < 4; ++c) acc[mi][nj][c] = 0.f;

    uint32_t arow, brow, aku0, bku0, sw;
    frag_bases(smb, lane, wm, wn, arow, brow, aku0, bku0, sw);
    mma_tile(acc, arow, brow, aku0, bku0, sw);

    // add bias into accumulators (so stats see h directly)
    const float* bias = b1g + r * FF;
#pragma unroll
    for (int nj = 0; nj < 4; ++nj) {
        int col = wn + nj * 8 + 2 * tq;
        float bx = bias[col], by = bias[col + 1];
#pragma unroll
        for (int mi = 0; mi < 2; ++mi) {
            acc[mi][nj][0] += bx; acc[mi][nj][1] += by;
            acc[mi][nj][2] += bx; acc[mi][nj][3] += by;
        }
    }

    // store h
    float* H = g_h + (size_t)r * (NN * FF);
#pragma unroll
    for (int mi = 0; mi < 2; ++mi) {
        int ra = row0 + wm + mi * 16 + gq;
#pragma unroll
        for (int nj = 0; nj < 4; ++nj) {
            int col = wn + nj * 8 + 2 * tq;
            if (ra < NN)
                *(float2*)(H + (size_t)ra * FF + col) = make_float2(acc[mi][nj][0], acc[mi][nj][1]);
            if (ra + 8 < NN)
                *(float2*)(H + (size_t)(ra + 8) * FF + col) = make_float2(acc[mi][nj][2], acc[mi][nj][3]);
        }
    }

    // fused BN stats: per-column sum / sumsq of this tile
    __syncthreads();
    float* red = (float*)sm;  // [0,128) sum, [128,256) sumsq
    red[tid] = 0.f;
    __syncthreads();
#pragma unroll
    for (int nj = 0; nj < 4; ++nj)
#pragma unroll
        for (int par = 0; par < 2; ++par) {
            int col = wn + nj * 8 + 2 * tq + par;
            float s = 0.f, q = 0.f;
#pragma unroll
            for (int mi = 0; mi < 2; ++mi) {
                int ra = row0 + wm + mi * 16 + gq;
                if (ra < NN) {
                    float v = acc[mi][nj][par];
                    s += v; q = fmaf(v, v, q);
                }
                if (ra + 8 < NN) {
                    float v = acc[mi][nj][2 + par];
                    s += v; q = fmaf(v, v, q);
                }
            }
            atomicAdd(&red[col], s);
            atomicAdd(&red[128 + col], q);
        }
    __syncthreads();
    if (tid < 128) {
        atomicAdd(&g_sum[r * FF + tid], red[tid]);
        atomicAdd(&g_sumsq[r * FF + tid], red[128 + tid]);
    }
}

// ---------------- GEMM2: out = x@Wself + sum_r relu(bn(h_r))@W2[r] + bias ----------
// BN finalize fused: scale/shift/bias computed per-block into smem.
__global__ __launch_bounds__(256, 2) void gemm2_tc(const float* __restrict__ x,
                                                   const float* __restrict__ gamma,
                                                   const float* __restrict__ beta,
                                                   const float* __restrict__ bself,
                                                   const float* __restrict__ b2g,
                                                   float* __restrict__ out) {
    extern __shared__ unsigned sm[];
    unsigned* Ah = sm;
    unsigned* Al = sm + 4096;
    float* s_scale = (float*)(sm + 24576);
    float* s_shift = (float*)(sm + 25088);
    float* s_bias  = (float*)(sm + 25600);
    const uint32_t smb = smem_u32(sm);
    const int tid = threadIdx.x, wid = tid >> 5, lane = tid & 31;
    const int gq = lane >> 2, tq = lane & 3;
    const int wm = (wid & 1) * 32, wn = (wid >> 1) * 32;
    const int row0 = blockIdx.x * 64;

    // fused BN finalize (reads gemm1's global stats)
    for (int i = tid; i < RR * FF; i += 256) {
        float inv_n = 1.0f / (float)NN;
        float mean = g_sum[i] * inv_n;
        float var = g_sumsq[i] * inv_n - mean * mean;
        if (var < 0.f) var = 0.f;
        float scv = gamma[i] * rsqrtf(var + 1e-5f);
        s_scale[i] = scv;
        s_shift[i] = beta[i] - mean * scv;
    }
    for (int i = tid; i < FF; i += 256) {
        float b = bself[i];
#pragma unroll
        for (int rr = 0; rr < RR; ++rr) b += b2g[rr * FF + i];
        s_bias[i] = b;
    }

    float acc[2][4][4];
#pragma unroll
    for (int mi = 0; mi < 2; ++mi)
#pragma unroll
        for (int nj = 0; nj < 4; ++nj)
#pragma unroll
            for (int c = 0; c < 4; ++c) acc[mi][nj][c] = 0.f;

    uint32_t arow, brow, aku0, bku0, sw;
    frag_bases(smb, lane, wm, wn, arow, brow, aku0, bku0, sw);

    for (int rel = 0; rel < 5; ++rel) {
        __syncthreads();
        copy_b_async(smb, 4 + rel, tid);

        const float* A = (rel == 0) ? x : (g_h + (size_t)(rel - 1) * (NN * FF));
        const float* sc = s_scale + (rel - 1) * FF;
        const float* sf = s_shift + (rel - 1) * FF;
#pragma unroll
        for (int it = 0; it < 8; ++it) {
            int q = it * 256 + tid;
            int row = q >> 5, c4 = q & 31, k4 = c4 * 4;
            float4 v = make_float4(0.f, 0.f, 0.f, 0.f);
            int grow = row0 + row;
            if (grow < NN) {
                v = ((const float4*)A)[(size_t)grow * 32 + c4];
                if (rel > 0) {
                    v.x = fmaxf(fmaf(v.x, sc[k4 + 0], sf[k4 + 0]), 0.f);
                    v.y = fmaxf(fmaf(v.y, sc[k4 + 1], sf[k4 + 1]), 0.f);
                    v.z = fmaxf(fmaf(v.z, sc[k4 + 2], sf[k4 + 2]), 0.f);
                    v.w = fmaxf(fmaf(v.w, sc[k4 + 3], sf[k4 + 3]), 0.f);
                }
            }
            unsigned h0, l0, h1, l1;
            split2(v.x, v.y, h0, l0);
            split2(v.z, v.w, h1, l1);
            int idx = row * 64 + ((c4 * 2) ^ ((row & 7) << 2));
            Ah[idx] = h0; Ah[idx + 1] = h1;
            Al[idx] = l0; Al[idx + 1] = l1;
        }
        CP_WAIT();
        __syncthreads();

        mma_tile(acc, arow, brow, aku0, bku0, sw);
    }

#pragma unroll
    for (int mi = 0; mi < 2; ++mi) {
        int ra = row0 + wm + mi * 16 + gq;
#pragma unroll
        for (int nj = 0; nj < 4; ++nj) {
            int col = wn + nj * 8 + 2 * tq;
            float bx = s_bias[col], by = s_bias[col + 1];
            if (ra < NN)
                *(float2*)(out + (size_t)ra * FF + col) =
                    make_float2(acc[mi][nj][0] + bx, acc[mi][nj][1] + by);
            if (ra + 8 < NN)
                *(float2*)(out + (size_t)(ra + 8) * FF + col) =
                    make_float2(acc[mi][nj][2] + bx, acc[mi][nj][3] + by);
        }
    }
}

// ---------------- launch ---------------------------------------------------------
extern "C" void kernel_launch(void* const* d_in, const int* in_sizes, int n_in,
                              void* d_out, int out_size) {
    const float* x     = (const float*)d_in[0];
    const int*   ei    = (const int*)d_in[1];
    const int*   et    = (const int*)d_in[2];
    const float* Wself = (const float*)d_in[3];
    const float* bself = (const float*)d_in[4];
    const float* W1    = (const float*)d_in[5];
    const float* b1    = (const float*)d_in[6];
    const float* gamma = (const float*)d_in[7];
    const float* beta  = (const float*)d_in[8];
    const float* W2    = (const float*)d_in[9];
    const float* b2    = (const float*)d_in[10];
    float* out = (float*)d_out;

    void* p_agg = nullptr;
    cudaGetSymbolAddress(&p_agg, g_agg);
    cudaMemsetAsync(p_agg, 0, (size_t)RR * NN * FF * sizeof(float));

    cudaFuncSetAttribute(gemm1_tc, cudaFuncAttributeMaxDynamicSharedMemorySize, SMEM1_BYTES);
    cudaFuncSetAttribute(gemm2_tc, cudaFuncAttributeMaxDynamicSharedMemorySize, SMEM2_BYTES);

    const int G1 = (NN + 63) / 64;  // 782

    prep_w_kernel<<<9, 256>>>(W1, Wself, W2);
    scatter_kernel<<<(EE * 32) / 256, 256>>>(ei, et, (const float4*)x);
    gemm1_tc<<<dim3(G1, RR), 256, SMEM1_BYTES>>>((const float4*)x, b1);
    gemm2_tc<<<G1, 256, SMEM2_BYTES>>>(x, gamma, beta, bself, b2, out);  // 4th: profiled
}